// round 11
// baseline (speedup 1.0000x reference)
#include <cuda_runtime.h>
#include <cuda_fp16.h>
#include <math.h>
#include <stdint.h>

// ---------------- problem constants ----------------
#define Nn      32768
#define Ll      3000
#define PERG    64
#define NG      512          // Nn / PERG
#define DEGc    16
#define Ec      (Nn*DEGc)    // 524288
#define HIDc    128
#define OUT3c   64
#define REDc    146
#define FINc    4672         // 32*146
#define EPSf    1e-5f
#define TILES   146          // FINc / 32

// ---------------- device scratch (static, no allocs) ----------------
__device__ float g_A[NG*64*64];                 // 8 MB
__device__ __half g_h0[(size_t)Nn * FINc];      // 306 MB (fp16 conv output)
__device__ __half g_h1[(size_t)Nn * HIDc];      // 8 MB (fp16 layer1 output)
__device__ __half g_Wt[(size_t)HIDc * FINc];    // 1.2 MB: W1^T, fp16
__device__ uint4  g_Wfrag[7*2*32];              // conv A-fragments [k16][mi][lane]
__device__ __half g_W2t[HIDc*HIDc];             // W2^T [n][k] fp16
__device__ __half g_W3t[OUT3c*HIDc];            // W3^T [n][k] fp16

// ---------------- helpers ----------------
__device__ __forceinline__ uint32_t smem_u32(const void* p) {
    uint32_t a;
    asm("{ .reg .u64 t; cvta.to.shared.u64 t, %1; cvt.u32.u64 %0, t; }" : "=r"(a) : "l"(p));
    return a;
}
__device__ __forceinline__ void mma_f16(float* d, const uint32_t* a, uint32_t b0, uint32_t b1) {
    asm volatile(
        "mma.sync.aligned.m16n8k16.row.col.f32.f16.f16.f32 "
        "{%0,%1,%2,%3}, {%4,%5,%6,%7}, {%8,%9}, {%0,%1,%2,%3};"
        : "+f"(d[0]), "+f"(d[1]), "+f"(d[2]), "+f"(d[3])
        : "r"(a[0]), "r"(a[1]), "r"(a[2]), "r"(a[3]), "r"(b0), "r"(b1));
}
__device__ __forceinline__ void cp16(uint32_t dst, const void* src) {
    asm volatile("cp.async.cg.shared.global [%0], [%1], 16;" :: "r"(dst), "l"(src));
}
#define CP_COMMIT() asm volatile("cp.async.commit_group;" ::: "memory")
#define CP_WAIT1()  asm volatile("cp.async.wait_group 1;" ::: "memory")
__device__ __forceinline__ uint32_t h2u(__half2 h) {
    return *reinterpret_cast<uint32_t*>(&h);
}

// ---------------- per-graph aggregation matrix (deg computed locally) ----------------
__global__ void __launch_bounds__(256) k_buildA(const int* __restrict__ src,
                                                const int* __restrict__ dst,
                                                const float* __restrict__ w) {
    __shared__ float sA[64*64];
    __shared__ float sdeg[64];
    const int g = blockIdx.x, tid = threadIdx.x;
    for (int i = tid; i < 4096; i += 256) sA[i] = 0.f;
    if (tid < 64) sdeg[tid] = 1.0f;
    __syncthreads();
    const int base = g * (PERG * DEGc);
    for (int e = tid; e < PERG*DEGc; e += 256)
        atomicAdd(&sdeg[dst[base + e] - g*64], w[base + e]);
    __syncthreads();
    if (tid < 64) sdeg[tid] = rsqrtf(sdeg[tid]);
    __syncthreads();
    for (int e = tid; e < PERG*DEGc; e += 256) {
        int s = src[base + e] - g*64;
        int d = dst[base + e] - g*64;
        atomicAdd(&sA[d*64 + s], sdeg[s] * w[base + e] * sdeg[d]);
    }
    __syncthreads();
    if (tid < 64) { float di = sdeg[tid]; sA[tid*64 + tid] += di*di; }
    __syncthreads();
    for (int i = tid; i < 4096; i += 256) g_A[g*4096 + i] = sA[i];
}

// ---------------- W1 transpose + fp16 round ----------------
__global__ void k_wt(const float* __restrict__ W) {
    __shared__ float t[32][33];
    int k0 = blockIdx.x * 32, n0 = blockIdx.y * 32;
    int tx = threadIdx.x, ty = threadIdx.y;           // 32 x 8
    for (int r = 0; r < 32; r += 8)
        t[ty + r][tx] = W[(size_t)(k0 + ty + r) * HIDc + n0 + tx];
    __syncthreads();
    for (int r = 0; r < 32; r += 8)
        g_Wt[(size_t)(n0 + ty + r) * FINc + k0 + tx] = __float2half_rn(t[tx][ty + r]);
}

// ---------------- weight prep: conv A-fragments + W2^T + W3^T ----------------
__global__ void k_wprep(const float* __restrict__ cw,
                        const float* __restrict__ W2,
                        const float* __restrict__ W3) {
    int i = blockIdx.x * blockDim.x + threadIdx.x;
    if (i < 7*2*32) {
        int k16 = i / 64, mi = (i >> 5) & 1, lane = i & 31;
        int gID = lane >> 2, tig = lane & 3;
        int c = mi*16 + gID;
        int k0 = k16 * 16;
        auto wv = [&](int cc, int t) -> __half {
            return __float2half_rn((t < 100) ? cw[cc*100 + t] : 0.f);
        };
        auto pk2 = [&](int cc, int t) -> uint32_t {
            __half2 h = __halves2half2(wv(cc, t), wv(cc, t + 1));
            return *reinterpret_cast<uint32_t*>(&h);
        };
        uint4 pk;
        pk.x = pk2(c,     k0 + 2*tig);
        pk.y = pk2(c + 8, k0 + 2*tig);
        pk.z = pk2(c,     k0 + 8 + 2*tig);
        pk.w = pk2(c + 8, k0 + 8 + 2*tig);
        g_Wfrag[i] = pk;
    }
    int j = i - 7*2*32;
    if (j >= 0 && j < HIDc*HIDc) {
        int n = j >> 7, k = j & 127;
        g_W2t[j] = __float2half_rn(W2[k*HIDc + n]);
    }
    int l = j - HIDc*HIDc;
    if (l >= 0 && l < OUT3c*HIDc) {
        int n = l >> 7, k = l & 127;
        g_W3t[l] = __float2half_rn(W3[k*OUT3c + n]);
    }
}

// ---------------- Conv1d via mma.sync fp16; A-fragments in registers ----------------
// One CTA (128 thr, 4 warps) per node. M=32 filters, N=160 p (warp=40),
// K=112 (7 k16 steps). B = implicit im2col from xs; A = register fragments.
__global__ void __launch_bounds__(128) k_conv_tc(const float* __restrict__ x,
                                                 const float* __restrict__ cb) {
    __shared__ __align__(16) __half sbuf[4672];   // xs in [0,3304); reused as sout (4672)
    __half* xs = sbuf;
    const int n    = blockIdx.x;
    const int tid  = threadIdx.x;
    const int warp = tid >> 5, lane = tid & 31;
    const int gID  = lane >> 2, tig = lane & 3;

    // A fragments -> registers (identical across CTAs; L1/L2 broadcast)
    uint4 aw[2][7];
#pragma unroll
    for (int k16 = 0; k16 < 7; k16++) {
        aw[0][k16] = g_Wfrag[(k16*2 + 0)*32 + lane];
        aw[1][k16] = g_Wfrag[(k16*2 + 1)*32 + lane];
    }

    {
        const float4* x4 = reinterpret_cast<const float4*>(x + (size_t)n * Ll);
        for (int i = tid; i < 750; i += 128) {
            float4 v = x4[i];
            __half2* d = reinterpret_cast<__half2*>(xs + i*4);
            d[0] = __floats2half2_rn(v.x, v.y);
            d[1] = __floats2half2_rn(v.z, v.w);
        }
        __half2 z2 = __floats2half2_rn(0.f, 0.f);
        for (int i = 1500 + tid; i < 1652; i += 128)
            reinterpret_cast<__half2*>(xs)[i] = z2;
    }
    __syncthreads();

    float acc[2][5][4];
#pragma unroll
    for (int mi = 0; mi < 2; mi++)
#pragma unroll
        for (int nt = 0; nt < 5; nt++)
#pragma unroll
            for (int c = 0; c < 4; c++) acc[mi][nt][c] = 0.f;

    const int pbase = warp * 40;
#pragma unroll
    for (int k16 = 0; k16 < 7; k16++) {
        const int k0 = k16 * 16;
        const uint32_t* a0 = reinterpret_cast<const uint32_t*>(&aw[0][k16]);
        const uint32_t* a1 = reinterpret_cast<const uint32_t*>(&aw[1][k16]);
#pragma unroll
        for (int nt = 0; nt < 5; nt++) {
            const int p = pbase + nt*8 + gID;
            uint32_t b0 = *reinterpret_cast<const uint32_t*>(xs + 20*p + k0 + 2*tig);
            uint32_t b1 = *reinterpret_cast<const uint32_t*>(xs + 20*p + k0 + 8 + 2*tig);
            mma_f16(acc[0][nt], a0, b0, b1);
            mma_f16(acc[1][nt], a1, b0, b1);
        }
    }

    float bc[2][2];
#pragma unroll
    for (int mi = 0; mi < 2; mi++) {
        bc[mi][0] = cb[mi*16 + gID];
        bc[mi][1] = cb[mi*16 + gID + 8];
    }
    __syncthreads();
    __half* sout = sbuf;                   // 4672 fp16 [c][p]
#pragma unroll
    for (int mi = 0; mi < 2; mi++)
#pragma unroll
        for (int nt = 0; nt < 5; nt++) {
            const int c0 = mi*16 + gID, c1 = c0 + 8;
            const int p0 = pbase + nt*8 + 2*tig;
            if (p0 < REDc) {
                bool two = (p0 + 1 < REDc);
                float v00 = fmaxf(acc[mi][nt][0] + bc[mi][0], 0.f);
                float v01 = two ? fmaxf(acc[mi][nt][1] + bc[mi][0], 0.f) : 0.f;
                float v10 = fmaxf(acc[mi][nt][2] + bc[mi][1], 0.f);
                float v11 = two ? fmaxf(acc[mi][nt][3] + bc[mi][1], 0.f) : 0.f;
                if (two) {
                    *reinterpret_cast<__half2*>(sout + c0*REDc + p0) = __floats2half2_rn(v00, v01);
                    *reinterpret_cast<__half2*>(sout + c1*REDc + p0) = __floats2half2_rn(v10, v11);
                } else {
                    sout[c0*REDc + p0] = __float2half_rn(v00);
                    sout[c1*REDc + p0] = __float2half_rn(v10);
                }
            }
        }
    __syncthreads();
    uint4* o4 = reinterpret_cast<uint4*>(g_h0 + (size_t)n * FINc);
    const uint4* so4 = reinterpret_cast<const uint4*>(sout);
    for (int i = tid; i < 584; i += 128) o4[i] = so4[i];
}

// ---------------- layer1 via mma.sync fp16 (m16n8k16), fp16 output ----------------
__global__ void __launch_bounds__(256, 2) k_layer1_hf(
    const float* __restrict__ bias,
    const float* __restrict__ gam, const float* __restrict__ bet,
    const float* __restrict__ mean, const float* __restrict__ var)
{
    extern __shared__ float smf[];
    const uint32_t sb = smem_u32(smf);
    const int tid  = threadIdx.x;
    const int b    = blockIdx.x;
    const int warp = tid >> 5, lane = tid & 31;
    const int wm   = warp >> 1, wn = warp & 1;
    const int gID  = lane >> 2, tig = lane & 3;

    const __half* Ap = g_h0 + (size_t)b * 128 * FINc;
    const int lr = tid >> 1;
    const int lc = (tid & 1) * 16;

    auto issue = [&](int i) {
        const int s = i & 1;
        const int k0 = i * 32;
        const uint32_t stb = sb + (uint32_t)s * 20480u;
#pragma unroll
        for (int q = 0; q < 2; q++) {
            int c = lc + q * 8;
            uint32_t o = (uint32_t)(lr * 80 + c * 2);
            cp16(stb + o,          Ap   + (size_t)lr * FINc + k0 + c);
            cp16(stb + 10240u + o, g_Wt + (size_t)lr * FINc + k0 + c);
        }
    };

    float acc[2][8][4];
#pragma unroll
    for (int mi = 0; mi < 2; mi++)
#pragma unroll
        for (int j = 0; j < 8; j++)
#pragma unroll
            for (int c = 0; c < 4; c++) acc[mi][j][c] = 0.f;

    issue(0); CP_COMMIT();
    issue(1); CP_COMMIT();

    for (int i = 0; i < TILES; i++) {
        CP_WAIT1();
        __syncthreads();
        const __half* As = reinterpret_cast<const __half*>(
            reinterpret_cast<const char*>(smf) + (i & 1) * 20480);
        const __half* Bs = As + 5120;
#pragma unroll
        for (int kk = 0; kk < 2; kk++) {
            const int k0 = kk * 16;
            uint32_t a[2][4];
#pragma unroll
            for (int mi = 0; mi < 2; mi++) {
                int row = wm*32 + mi*16 + gID;
                a[mi][0] = *reinterpret_cast<const uint32_t*>(As + row*40     + k0 + 2*tig);
                a[mi][1] = *reinterpret_cast<const uint32_t*>(As + (row+8)*40 + k0 + 2*tig);
                a[mi][2] = *reinterpret_cast<const uint32_t*>(As + row*40     + k0 + 8 + 2*tig);
                a[mi][3] = *reinterpret_cast<const uint32_t*>(As + (row+8)*40 + k0 + 8 + 2*tig);
            }
#pragma unroll
            for (int j = 0; j < 8; j++) {
                int n = wn*64 + j*8 + gID;
                uint32_t b0 = *reinterpret_cast<const uint32_t*>(Bs + n*40 + k0 + 2*tig);
                uint32_t b1 = *reinterpret_cast<const uint32_t*>(Bs + n*40 + k0 + 8 + 2*tig);
                mma_f16(acc[0][j], a[0], b0, b1);
                mma_f16(acc[1][j], a[1], b0, b1);
            }
        }
        __syncthreads();
        if (i + 2 < TILES) issue(i + 2);
        CP_COMMIT();
    }

    __syncthreads();
    float* Zs = smf;                               // 128 x 130
    float* Ag = smf + 16640;                       // 2 x (64 x 65)
#pragma unroll
    for (int mi = 0; mi < 2; mi++)
#pragma unroll
        for (int j = 0; j < 8; j++) {
            int row = wm*32 + mi*16 + gID;
            int col = wn*64 + j*8 + 2*tig;
            *reinterpret_cast<float2*>(Zs + row*130 + col) =
                make_float2(acc[mi][j][0], acc[mi][j][1]);
            *reinterpret_cast<float2*>(Zs + (row+8)*130 + col) =
                make_float2(acc[mi][j][2], acc[mi][j][3]);
        }
    {
        const float* gA = g_A + (size_t)(2*b) * 4096;
        for (int i2 = tid; i2 < 8192; i2 += 256) {
            int gg = i2 >> 12, rr = (i2 >> 6) & 63, cc = i2 & 63;
            Ag[gg*4160 + rr*65 + cc] = gA[(size_t)gg*4096 + rr*64 + cc];
        }
    }
    __syncthreads();

    {
        const int gg = tid >> 7;
        const int t  = tid & 127;
        const int tx = t & 15;
        const int ty = t >> 4;
        float ac[8][8];
#pragma unroll
        for (int r = 0; r < 8; r++)
#pragma unroll
            for (int j = 0; j < 8; j++) ac[r][j] = 0.f;

        const float* Agg = Ag + gg * 4160;
        const float* Zg  = Zs + gg * 64 * 130;
#pragma unroll 4
        for (int k = 0; k < 64; k++) {
            float a[8], z[8];
#pragma unroll
            for (int r = 0; r < 8; r++) a[r] = Agg[(ty*8 + r)*65 + k];
#pragma unroll
            for (int j = 0; j < 8; j++) z[j] = Zg[k*130 + tx*8 + j];
#pragma unroll
            for (int r = 0; r < 8; r++)
#pragma unroll
                for (int j = 0; j < 8; j++)
                    ac[r][j] = fmaf(a[r], z[j], ac[r][j]);
        }
        float sc[8], sh[8];
#pragma unroll
        for (int j = 0; j < 8; j++) {
            int col = tx*8 + j;
            float s = gam[col] * rsqrtf(var[col] + EPSf);
            sc[j] = s;
            sh[j] = (bias[col] - mean[col]) * s + bet[col];
        }
#pragma unroll
        for (int r = 0; r < 8; r++) {
            float v[8];
#pragma unroll
            for (int j = 0; j < 8; j++)
                v[j] = fmaxf(fmaf(ac[r][j], sc[j], sh[j]), 0.f);
            uint4 pk;
            pk.x = h2u(__floats2half2_rn(v[0], v[1]));
            pk.y = h2u(__floats2half2_rn(v[2], v[3]));
            pk.z = h2u(__floats2half2_rn(v[4], v[5]));
            pk.w = h2u(__floats2half2_rn(v[6], v[7]));
            *reinterpret_cast<uint4*>(g_h1 + (size_t)(b*128 + gg*64 + ty*8 + r)*HIDc + tx*8) = pk;
        }
    }
}

// ---------------- fused layers 2+3 + head; GEMMs on fp16 MMA ----------------
__global__ void __launch_bounds__(256) k_layer23(
    const float* __restrict__ b2,
    const float* __restrict__ g2, const float* __restrict__ be2,
    const float* __restrict__ m2, const float* __restrict__ v2,
    const float* __restrict__ b3,
    const float* __restrict__ g3, const float* __restrict__ be3,
    const float* __restrict__ m3, const float* __restrict__ v3,
    const float* __restrict__ fcw, const float* __restrict__ fcb,
    float* __restrict__ out)
{
    extern __shared__ float sm[];
    float* Ag = sm;              // 64 x 65
    float* Zs = sm + 4160;       // 64 x 132 fp32 (later 64 x 68)
    __half* Hh = reinterpret_cast<__half*>(sm + 12608);   // 64 x 136 halves

    const int tid = threadIdx.x;
    const int g   = blockIdx.x;
    const int warp = tid >> 5, lane = tid & 31;
    const int wm = warp >> 2, wn = warp & 3;
    const int gID = lane >> 2, tig = lane & 3;
    const int tx = tid & 15, ty = tid >> 4;

    for (int i = tid; i < 4096; i += 256)
        Ag[(i >> 6)*65 + (i & 63)] = g_A[(size_t)g*4096 + i];
    {
        const uint4* src = reinterpret_cast<const uint4*>(g_h1 + (size_t)g * 64 * HIDc);
        for (int i = tid; i < 1024; i += 256) {
            int row = i >> 4, c8 = i & 15;
            *reinterpret_cast<uint4*>(Hh + row*136 + c8*8) = src[i];
        }
    }
    __syncthreads();

    // ---- phase 1 (MMA): Z2 = H1 @ W2 ----
    float acc[2][4][4];
#pragma unroll
    for (int mi = 0; mi < 2; mi++)
#pragma unroll
        for (int j = 0; j < 4; j++)
#pragma unroll
            for (int c = 0; c < 4; c++) acc[mi][j][c] = 0.f;
#pragma unroll
    for (int k16 = 0; k16 < 8; k16++) {
        const int k0 = k16 * 16;
        uint32_t a[2][4];
#pragma unroll
        for (int mi = 0; mi < 2; mi++) {
            int row = wm*32 + mi*16 + gID;
            a[mi][0] = *reinterpret_cast<const uint32_t*>(Hh + row*136     + k0 + 2*tig);
            a[mi][1] = *reinterpret_cast<const uint32_t*>(Hh + (row+8)*136 + k0 + 2*tig);
            a[mi][2] = *reinterpret_cast<const uint32_t*>(Hh + row*136     + k0 + 8 + 2*tig);
            a[mi][3] = *reinterpret_cast<const uint32_t*>(Hh + (row+8)*136 + k0 + 8 + 2*tig);
        }
#pragma unroll
        for (int j = 0; j < 4; j++) {
            int n = wn*32 + j*8 + gID;
            uint32_t b0 = __ldg(reinterpret_cast<const uint32_t*>(g_W2t + n*HIDc + k0 + 2*tig));
            uint32_t b1 = __ldg(reinterpret_cast<const uint32_t*>(g_W2t + n*HIDc + k0 + 8 + 2*tig));
            mma_f16(acc[0][j], a[0], b0, b1);
            mma_f16(acc[1][j], a[1], b0, b1);
        }
    }
    __syncthreads();
#pragma unroll
    for (int mi = 0; mi < 2; mi++)
#pragma unroll
        for (int j = 0; j < 4; j++) {
            int row = wm*32 + mi*16 + gID;
            int col = wn*32 + j*8 + 2*tig;
            *reinterpret_cast<float2*>(Zs + row*132 + col) =
                make_float2(acc[mi][j][0], acc[mi][j][1]);
            *reinterpret_cast<float2*>(Zs + (row+8)*132 + col) =
                make_float2(acc[mi][j][2], acc[mi][j][3]);
        }
    __syncthreads();

    // ---- phase 2 (fp32): H2 = relu(BN2(A@Z2 + b2)) -> Hh (fp16) ----
    {
        float ac[4][8];
#pragma unroll
        for (int r = 0; r < 4; r++)
#pragma unroll
            for (int j = 0; j < 8; j++) ac[r][j] = 0.f;
#pragma unroll 4
        for (int k = 0; k < 64; k++) {
            float a[4];
#pragma unroll
            for (int r = 0; r < 4; r++) a[r] = Ag[(ty*4 + r)*65 + k];
            float zz[8];
            *reinterpret_cast<float4*>(zz)     = *reinterpret_cast<const float4*>(Zs + k*132 + tx*8);
            *reinterpret_cast<float4*>(zz + 4) = *reinterpret_cast<const float4*>(Zs + k*132 + tx*8 + 4);
#pragma unroll
            for (int r = 0; r < 4; r++)
#pragma unroll
                for (int j = 0; j < 8; j++)
                    ac[r][j] = fmaf(a[r], zz[j], ac[r][j]);
        }
        float sc[8], sh[8];
#pragma unroll
        for (int j = 0; j < 8; j++) {
            int col = tx*8 + j;
            float s = g2[col] * rsqrtf(v2[col] + EPSf);
            sc[j] = s;
            sh[j] = (b2[col] - m2[col]) * s + be2[col];
        }
#pragma unroll
        for (int r = 0; r < 4; r++) {
            float v[8];
#pragma unroll
            for (int j = 0; j < 8; j++)
                v[j] = fmaxf(fmaf(ac[r][j], sc[j], sh[j]), 0.f);
            __half2* d = reinterpret_cast<__half2*>(Hh + (ty*4 + r)*136 + tx*8);
            d[0] = __floats2half2_rn(v[0], v[1]);
            d[1] = __floats2half2_rn(v[2], v[3]);
            d[2] = __floats2half2_rn(v[4], v[5]);
            d[3] = __floats2half2_rn(v[6], v[7]);
        }
    }
    __syncthreads();

    // ---- phase 3 (MMA): Z3 = H2 @ W3 ----
    float ac3[2][2][4];
#pragma unroll
    for (int mi = 0; mi < 2; mi++)
#pragma unroll
        for (int j = 0; j < 2; j++)
#pragma unroll
            for (int c = 0; c < 4; c++) ac3[mi][j][c] = 0.f;
#pragma unroll
    for (int k16 = 0; k16 < 8; k16++) {
        const int k0 = k16 * 16;
        uint32_t a[2][4];
#pragma unroll
        for (int mi = 0; mi < 2; mi++) {
            int row = wm*32 + mi*16 + gID;
            a[mi][0] = *reinterpret_cast<const uint32_t*>(Hh + row*136     + k0 + 2*tig);
            a[mi][1] = *reinterpret_cast<const uint32_t*>(Hh + (row+8)*136 + k0 + 2*tig);
            a[mi][2] = *reinterpret_cast<const uint32_t*>(Hh + row*136     + k0 + 8 + 2*tig);
            a[mi][3] = *reinterpret_cast<const uint32_t*>(Hh + (row+8)*136 + k0 + 8 + 2*tig);
        }
#pragma unroll
        for (int j = 0; j < 2; j++) {
            int n = wn*16 + j*8 + gID;
            uint32_t b0 = __ldg(reinterpret_cast<const uint32_t*>(g_W3t + n*HIDc + k0 + 2*tig));
            uint32_t b1 = __ldg(reinterpret_cast<const uint32_t*>(g_W3t + n*HIDc + k0 + 8 + 2*tig));
            mma_f16(ac3[0][j], a[0], b0, b1);
            mma_f16(ac3[1][j], a[1], b0, b1);
        }
    }
    __syncthreads();
#pragma unroll
    for (int mi = 0; mi < 2; mi++)
#pragma unroll
        for (int j = 0; j < 2; j++) {
            int row = wm*32 + mi*16 + gID;
            int col = wn*16 + j*8 + 2*tig;
            *reinterpret_cast<float2*>(Zs + row*68 + col) =
                make_float2(ac3[mi][j][0], ac3[mi][j][1]);
            *reinterpret_cast<float2*>(Zs + (row+8)*68 + col) =
                make_float2(ac3[mi][j][2], ac3[mi][j][3]);
        }
    __syncthreads();

    // ---- phase 4 (fp32): Y3 = relu(BN3(A@Z3 + b3)) -> Ys ----
    float* Ys = reinterpret_cast<float*>(Hh);
    {
        float ac[4][4];
#pragma unroll
        for (int r = 0; r < 4; r++)
#pragma unroll
            for (int j = 0; j < 4; j++) ac[r][j] = 0.f;
#pragma unroll 4
        for (int k = 0; k < 64; k++) {
            float a[4];
#pragma unroll
            for (int r = 0; r < 4; r++) a[r] = Ag[(ty*4 + r)*65 + k];
            float zz[4];
            *reinterpret_cast<float4*>(zz) = *reinterpret_cast<const float4*>(Zs + k*68 + tx*4);
#pragma unroll
            for (int r = 0; r < 4; r++)
#pragma unroll
                for (int j = 0; j < 4; j++)
                    ac[r][j] = fmaf(a[r], zz[j], ac[r][j]);
        }
        float sc[4], sh[4];
#pragma unroll
        for (int j = 0; j < 4; j++) {
            int col = tx*4 + j;
            float s = g3[col] * rsqrtf(v3[col] + EPSf);
            sc[j] = s;
            sh[j] = (b3[col] - m3[col]) * s + be3[col];
        }
        __syncthreads();
#pragma unroll
        for (int r = 0; r < 4; r++)
#pragma unroll
            for (int j = 0; j < 4; j++)
                Ys[(ty*4 + r)*64 + tx*4 + j] = fmaxf(fmaf(ac[r][j], sc[j], sh[j]), 0.f);
    }
    __syncthreads();

    // ---- pool + FC + log_softmax ----
    float* pooled = Ag;
    if (tid < 64) {
        float s = 0.f;
#pragma unroll 8
        for (int i = 0; i < 64; i++) s += Ys[i*64 + tid];
        pooled[tid] = s * (1.0f / 64.0f);
    }
    __syncthreads();
    if (tid < 2) {
        float l = fcb[tid];
#pragma unroll 8
        for (int j = 0; j < 64; j++) l = fmaf(pooled[j], fcw[j*2 + tid], l);
        pooled[64 + tid] = l;
    }
    __syncthreads();
    if (tid == 0) {
        float l0 = pooled[64], l1 = pooled[65];
        float m  = fmaxf(l0, l1);
        float lse = m + logf(expf(l0 - m) + expf(l1 - m));
        out[g*2 + 0] = l0 - lse;
        out[g*2 + 1] = l1 - lse;
    }
}

// ---------------- host launcher ----------------
extern "C" void kernel_launch(void* const* d_in, const int* in_sizes, int n_in,
                              void* d_out, int out_size) {
    const float* x   = (const float*)d_in[0];
    const int*   ei  = (const int*)  d_in[1];
    const float* ea  = (const float*)d_in[2];
    const float* cw  = (const float*)d_in[4];
    const float* cb  = (const float*)d_in[5];
    const float* W1  = (const float*)d_in[6];
    const float* b1  = (const float*)d_in[7];
    const float* W2  = (const float*)d_in[8];
    const float* b2  = (const float*)d_in[9];
    const float* W3  = (const float*)d_in[10];
    const float* b3  = (const float*)d_in[11];
    const float* g1  = (const float*)d_in[12];
    const float* be1 = (const float*)d_in[13];
    const float* m1  = (const float*)d_in[14];
    const float* v1  = (const float*)d_in[15];
    const float* g2  = (const float*)d_in[16];
    const float* be2 = (const float*)d_in[17];
    const float* m2  = (const float*)d_in[18];
    const float* v2  = (const float*)d_in[19];
    const float* g3  = (const float*)d_in[20];
    const float* be3 = (const float*)d_in[21];
    const float* m3  = (const float*)d_in[22];
    const float* v3  = (const float*)d_in[23];
    const float* fcw = (const float*)d_in[24];
    const float* fcb = (const float*)d_in[25];
    float* out = (float*)d_out;

    const int* srcp = ei;
    const int* dstp = ei + Ec;

    k_buildA<<<NG, 256>>>(srcp, dstp, ea);
    {
        dim3 tb(32, 8);
        dim3 gb(FINc/32, HIDc/32);
        k_wt<<<gb, tb>>>(W1);
    }
    {
        int tot = 7*2*32 + HIDc*HIDc + OUT3c*HIDc;
        k_wprep<<<(tot + 255)/256, 256>>>(cw, W2, W3);
    }
    k_conv_tc<<<Nn, 128>>>(x, cb);

    const int smemL1 = (128*130 + 2*64*65) * 4;   // 99840 B
    cudaFuncSetAttribute((const void*)k_layer1_hf,
                         cudaFuncAttributeMaxDynamicSharedMemorySize, smemL1);
    k_layer1_hf<<<NG/2, 256, smemL1>>>(b1, g1, be1, m1, v1);

    const int smemL23 = 16960 * 4;   // 67840 B
    cudaFuncSetAttribute((const void*)k_layer23,
                         cudaFuncAttributeMaxDynamicSharedMemorySize, smemL23);
    k_layer23<<<NG, 256, smemL23>>>(b2, g2, be2, m2, v2,
                                    b3, g3, be3, m3, v3, fcw, fcb, out);
}

// round 13
// speedup vs baseline: 1.1167x; 1.1167x over previous
#include <cuda_runtime.h>
#include <cuda_fp16.h>
#include <math.h>
#include <stdint.h>

// ---------------- problem constants ----------------
#define Nn      32768
#define Ll      3000
#define PERG    64
#define NG      512          // Nn / PERG
#define DEGc    16
#define Ec      (Nn*DEGc)    // 524288
#define HIDc    128
#define OUT3c   64
#define REDc    146
#define FINc    4672         // 32*146
#define EPSf    1e-5f
#define TILES   146          // FINc / 32
#define WCP     120          // conv weight pitch (halves)

// ---------------- device scratch (static, no allocs) ----------------
__device__ float g_A[NG*64*64];                 // 8 MB
__device__ __half g_h0[(size_t)Nn * FINc];      // 306 MB (fp16 conv output)
__device__ __half g_h1[(size_t)Nn * HIDc];      // 8 MB (fp16 layer1 output)
__device__ __half g_Wt[(size_t)HIDc * FINc];    // 1.2 MB: W1^T, fp16
__device__ __half g_Wch[32*WCP];                // conv weights fp16, pitch 120
__device__ __half g_W2t[HIDc*HIDc];             // W2^T [n][k] fp16
__device__ __half g_W3t[OUT3c*HIDc];            // W3^T [n][k] fp16

// ---------------- helpers ----------------
__device__ __forceinline__ uint32_t smem_u32(const void* p) {
    uint32_t a;
    asm("{ .reg .u64 t; cvta.to.shared.u64 t, %1; cvt.u32.u64 %0, t; }" : "=r"(a) : "l"(p));
    return a;
}
__device__ __forceinline__ void mma_f16(float* d, const uint32_t* a, uint32_t b0, uint32_t b1) {
    asm volatile(
        "mma.sync.aligned.m16n8k16.row.col.f32.f16.f16.f32 "
        "{%0,%1,%2,%3}, {%4,%5,%6,%7}, {%8,%9}, {%0,%1,%2,%3};"
        : "+f"(d[0]), "+f"(d[1]), "+f"(d[2]), "+f"(d[3])
        : "r"(a[0]), "r"(a[1]), "r"(a[2]), "r"(a[3]), "r"(b0), "r"(b1));
}
__device__ __forceinline__ void cp16(uint32_t dst, const void* src) {
    asm volatile("cp.async.cg.shared.global [%0], [%1], 16;" :: "r"(dst), "l"(src));
}
#define CP_COMMIT() asm volatile("cp.async.commit_group;" ::: "memory")
#define CP_WAIT1()  asm volatile("cp.async.wait_group 1;" ::: "memory")
__device__ __forceinline__ uint32_t h2u(__half2 h) {
    return *reinterpret_cast<uint32_t*>(&h);
}

// ---------------- per-graph aggregation matrix (deg computed locally) ----------------
__global__ void __launch_bounds__(256) k_buildA(const int* __restrict__ src,
                                                const int* __restrict__ dst,
                                                const float* __restrict__ w) {
    __shared__ float sA[64*64];
    __shared__ float sdeg[64];
    const int g = blockIdx.x, tid = threadIdx.x;
    for (int i = tid; i < 4096; i += 256) sA[i] = 0.f;
    if (tid < 64) sdeg[tid] = 1.0f;
    __syncthreads();
    const int base = g * (PERG * DEGc);
    for (int e = tid; e < PERG*DEGc; e += 256)
        atomicAdd(&sdeg[dst[base + e] - g*64], w[base + e]);
    __syncthreads();
    if (tid < 64) sdeg[tid] = rsqrtf(sdeg[tid]);
    __syncthreads();
    for (int e = tid; e < PERG*DEGc; e += 256) {
        int s = src[base + e] - g*64;
        int d = dst[base + e] - g*64;
        atomicAdd(&sA[d*64 + s], sdeg[s] * w[base + e] * sdeg[d]);
    }
    __syncthreads();
    if (tid < 64) { float di = sdeg[tid]; sA[tid*64 + tid] += di*di; }
    __syncthreads();
    for (int i = tid; i < 4096; i += 256) g_A[g*4096 + i] = sA[i];
}

// ---------------- W1 transpose + fp16 round ----------------
__global__ void k_wt(const float* __restrict__ W) {
    __shared__ float t[32][33];
    int k0 = blockIdx.x * 32, n0 = blockIdx.y * 32;
    int tx = threadIdx.x, ty = threadIdx.y;           // 32 x 8
    for (int r = 0; r < 32; r += 8)
        t[ty + r][tx] = W[(size_t)(k0 + ty + r) * HIDc + n0 + tx];
    __syncthreads();
    for (int r = 0; r < 32; r += 8)
        g_Wt[(size_t)(n0 + ty + r) * FINc + k0 + tx] = __float2half_rn(t[tx][ty + r]);
}

// ---------------- weight prep: conv weights + W2^T + W3^T ----------------
__global__ void k_wprep(const float* __restrict__ cw,
                        const float* __restrict__ W2,
                        const float* __restrict__ W3) {
    int i = blockIdx.x * blockDim.x + threadIdx.x;
    if (i < 32*WCP) {
        int c = i / WCP, t = i % WCP;
        g_Wch[i] = __float2half_rn((t < 100) ? cw[c*100 + t] : 0.f);
    }
    int j = i - 32*WCP;
    if (j >= 0 && j < HIDc*HIDc) {
        int n = j >> 7, k = j & 127;
        g_W2t[j] = __float2half_rn(W2[k*HIDc + n]);
    }
    int l = j - HIDc*HIDc;
    if (l >= 0 && l < OUT3c*HIDc) {
        int n = l >> 7, k = l & 127;
        g_W3t[l] = __float2half_rn(W3[k*OUT3c + n]);
    }
}

// ---------------- Conv1d via mma.sync fp16 (m16n8k16), direct STG epilogue ----------------
// One CTA (128 thr, 4 warps) per node. M=32 filters, N=160 p (warp=40),
// K=112 (7 k16 steps). B fragment = implicit im2col: B[k=t][n=p] = xs[20p + t].
__global__ void __launch_bounds__(128) k_conv_tc(const float* __restrict__ x,
                                                 const float* __restrict__ cb) {
    __shared__ __half sbuf[3304 + 32*WCP];   // xs [0,3304) ; ws [3304,+3840)
    __half* xs = sbuf;
    __half* ws = sbuf + 3304;
    const int n    = blockIdx.x;
    const int tid  = threadIdx.x;
    const int warp = tid >> 5, lane = tid & 31;
    const int gID  = lane >> 2, tig = lane & 3;

    {
        const float4* x4 = reinterpret_cast<const float4*>(x + (size_t)n * Ll);
        for (int i = tid; i < 750; i += 128) {
            float4 v = x4[i];
            __half2* d = reinterpret_cast<__half2*>(xs + i*4);
            d[0] = __floats2half2_rn(v.x, v.y);
            d[1] = __floats2half2_rn(v.z, v.w);
        }
        __half2 z2 = __floats2half2_rn(0.f, 0.f);
        for (int i = 1500 + tid; i < 1652; i += 128)
            reinterpret_cast<__half2*>(xs)[i] = z2;
        const uint4* w4 = reinterpret_cast<const uint4*>(g_Wch);
        uint4* ws4 = reinterpret_cast<uint4*>(ws);
        for (int i = tid; i < 480; i += 128) ws4[i] = w4[i];
    }
    __syncthreads();

    float acc[2][5][4];
#pragma unroll
    for (int mi = 0; mi < 2; mi++)
#pragma unroll
        for (int nt = 0; nt < 5; nt++)
#pragma unroll
            for (int c = 0; c < 4; c++) acc[mi][nt][c] = 0.f;

    const int pbase = warp * 40;
#pragma unroll
    for (int k16 = 0; k16 < 7; k16++) {
        const int k0 = k16 * 16;
        uint32_t a[2][4];
#pragma unroll
        for (int mi = 0; mi < 2; mi++) {
            const int c = mi*16 + gID;
            a[mi][0] = *reinterpret_cast<const uint32_t*>(ws + c*WCP     + k0 + 2*tig);
            a[mi][1] = *reinterpret_cast<const uint32_t*>(ws + (c+8)*WCP + k0 + 2*tig);
            a[mi][2] = *reinterpret_cast<const uint32_t*>(ws + c*WCP     + k0 + 8 + 2*tig);
            a[mi][3] = *reinterpret_cast<const uint32_t*>(ws + (c+8)*WCP + k0 + 8 + 2*tig);
        }
#pragma unroll
        for (int nt = 0; nt < 5; nt++) {
            const int p = pbase + nt*8 + gID;
            uint32_t b0 = *reinterpret_cast<const uint32_t*>(xs + 20*p + k0 + 2*tig);
            uint32_t b1 = *reinterpret_cast<const uint32_t*>(xs + 20*p + k0 + 8 + 2*tig);
            mma_f16(acc[0][nt], a[0], b0, b1);
            mma_f16(acc[1][nt], a[1], b0, b1);
        }
    }

    float bc[2][2];
#pragma unroll
    for (int mi = 0; mi < 2; mi++) {
        bc[mi][0] = cb[mi*16 + gID];
        bc[mi][1] = cb[mi*16 + gID + 8];
    }
    // Direct global stores: fragment (c, p0..p0+1) -> g_h0[n][c*146 + p0], half2.
    // p0 even and 146 even => 4B-aligned. tig 0..3 cover 16B contiguous per row.
    __half* op = g_h0 + (size_t)n * FINc;
#pragma unroll
    for (int mi = 0; mi < 2; mi++)
#pragma unroll
        for (int nt = 0; nt < 5; nt++) {
            const int c0 = mi*16 + gID, c1 = c0 + 8;
            const int p0 = pbase + nt*8 + 2*tig;
            if (p0 < REDc) {
                bool two = (p0 + 1 < REDc);
                float v00 = fmaxf(acc[mi][nt][0] + bc[mi][0], 0.f);
                float v10 = fmaxf(acc[mi][nt][2] + bc[mi][1], 0.f);
                if (two) {
                    float v01 = fmaxf(acc[mi][nt][1] + bc[mi][0], 0.f);
                    float v11 = fmaxf(acc[mi][nt][3] + bc[mi][1], 0.f);
                    *reinterpret_cast<__half2*>(op + c0*REDc + p0) = __floats2half2_rn(v00, v01);
                    *reinterpret_cast<__half2*>(op + c1*REDc + p0) = __floats2half2_rn(v10, v11);
                } else {
                    op[c0*REDc + p0] = __float2half_rn(v00);
                    op[c1*REDc + p0] = __float2half_rn(v10);
                }
            }
        }
}

// ---------------- layer1 via mma.sync fp16 (m16n8k16), fp16 output ----------------
__global__ void __launch_bounds__(256, 2) k_layer1_hf(
    const float* __restrict__ bias,
    const float* __restrict__ gam, const float* __restrict__ bet,
    const float* __restrict__ mean, const float* __restrict__ var)
{
    extern __shared__ float smf[];
    const uint32_t sb = smem_u32(smf);
    const int tid  = threadIdx.x;
    const int b    = blockIdx.x;
    const int warp = tid >> 5, lane = tid & 31;
    const int wm   = warp >> 1, wn = warp & 1;
    const int gID  = lane >> 2, tig = lane & 3;

    const __half* Ap = g_h0 + (size_t)b * 128 * FINc;
    const int lr = tid >> 1;
    const int lc = (tid & 1) * 16;

    auto issue = [&](int i) {
        const int s = i & 1;
        const int k0 = i * 32;
        const uint32_t stb = sb + (uint32_t)s * 20480u;
#pragma unroll
        for (int q = 0; q < 2; q++) {
            int c = lc + q * 8;
            uint32_t o = (uint32_t)(lr * 80 + c * 2);
            cp16(stb + o,          Ap   + (size_t)lr * FINc + k0 + c);
            cp16(stb + 10240u + o, g_Wt + (size_t)lr * FINc + k0 + c);
        }
    };

    float acc[2][8][4];
#pragma unroll
    for (int mi = 0; mi < 2; mi++)
#pragma unroll
        for (int j = 0; j < 8; j++)
#pragma unroll
            for (int c = 0; c < 4; c++) acc[mi][j][c] = 0.f;

    issue(0); CP_COMMIT();
    issue(1); CP_COMMIT();

    for (int i = 0; i < TILES; i++) {
        CP_WAIT1();
        __syncthreads();
        const __half* As = reinterpret_cast<const __half*>(
            reinterpret_cast<const char*>(smf) + (i & 1) * 20480);
        const __half* Bs = As + 5120;
#pragma unroll
        for (int kk = 0; kk < 2; kk++) {
            const int k0 = kk * 16;
            uint32_t a[2][4];
#pragma unroll
            for (int mi = 0; mi < 2; mi++) {
                int row = wm*32 + mi*16 + gID;
                a[mi][0] = *reinterpret_cast<const uint32_t*>(As + row*40     + k0 + 2*tig);
                a[mi][1] = *reinterpret_cast<const uint32_t*>(As + (row+8)*40 + k0 + 2*tig);
                a[mi][2] = *reinterpret_cast<const uint32_t*>(As + row*40     + k0 + 8 + 2*tig);
                a[mi][3] = *reinterpret_cast<const uint32_t*>(As + (row+8)*40 + k0 + 8 + 2*tig);
            }
#pragma unroll
            for (int j = 0; j < 8; j++) {
                int n = wn*64 + j*8 + gID;
                uint32_t b0 = *reinterpret_cast<const uint32_t*>(Bs + n*40 + k0 + 2*tig);
                uint32_t b1 = *reinterpret_cast<const uint32_t*>(Bs + n*40 + k0 + 8 + 2*tig);
                mma_f16(acc[0][j], a[0], b0, b1);
                mma_f16(acc[1][j], a[1], b0, b1);
            }
        }
        __syncthreads();
        if (i + 2 < TILES) issue(i + 2);
        CP_COMMIT();
    }

    __syncthreads();
    float* Zs = smf;                               // 128 x 130
    float* Ag = smf + 16640;                       // 2 x (64 x 65)
#pragma unroll
    for (int mi = 0; mi < 2; mi++)
#pragma unroll
        for (int j = 0; j < 8; j++) {
            int row = wm*32 + mi*16 + gID;
            int col = wn*64 + j*8 + 2*tig;
            *reinterpret_cast<float2*>(Zs + row*130 + col) =
                make_float2(acc[mi][j][0], acc[mi][j][1]);
            *reinterpret_cast<float2*>(Zs + (row+8)*130 + col) =
                make_float2(acc[mi][j][2], acc[mi][j][3]);
        }
    {
        const float* gA = g_A + (size_t)(2*b) * 4096;
        for (int i2 = tid; i2 < 8192; i2 += 256) {
            int gg = i2 >> 12, rr = (i2 >> 6) & 63, cc = i2 & 63;
            Ag[gg*4160 + rr*65 + cc] = gA[(size_t)gg*4096 + rr*64 + cc];
        }
    }
    __syncthreads();

    {
        const int gg = tid >> 7;
        const int t  = tid & 127;
        const int tx = t & 15;
        const int ty = t >> 4;
        float ac[8][8];
#pragma unroll
        for (int r = 0; r < 8; r++)
#pragma unroll
            for (int j = 0; j < 8; j++) ac[r][j] = 0.f;

        const float* Agg = Ag + gg * 4160;
        const float* Zg  = Zs + gg * 64 * 130;
#pragma unroll 4
        for (int k = 0; k < 64; k++) {
            float a[8], z[8];
#pragma unroll
            for (int r = 0; r < 8; r++) a[r] = Agg[(ty*8 + r)*65 + k];
#pragma unroll
            for (int j = 0; j < 8; j++) z[j] = Zg[k*130 + tx*8 + j];
#pragma unroll
            for (int r = 0; r < 8; r++)
#pragma unroll
                for (int j = 0; j < 8; j++)
                    ac[r][j] = fmaf(a[r], z[j], ac[r][j]);
        }
        float sc[8], sh[8];
#pragma unroll
        for (int j = 0; j < 8; j++) {
            int col = tx*8 + j;
            float s = gam[col] * rsqrtf(var[col] + EPSf);
            sc[j] = s;
            sh[j] = (bias[col] - mean[col]) * s + bet[col];
        }
#pragma unroll
        for (int r = 0; r < 8; r++) {
            float v[8];
#pragma unroll
            for (int j = 0; j < 8; j++)
                v[j] = fmaxf(fmaf(ac[r][j], sc[j], sh[j]), 0.f);
            uint4 pk;
            pk.x = h2u(__floats2half2_rn(v[0], v[1]));
            pk.y = h2u(__floats2half2_rn(v[2], v[3]));
            pk.z = h2u(__floats2half2_rn(v[4], v[5]));
            pk.w = h2u(__floats2half2_rn(v[6], v[7]));
            *reinterpret_cast<uint4*>(g_h1 + (size_t)(b*128 + gg*64 + ty*8 + r)*HIDc + tx*8) = pk;
        }
    }
}

// ---------------- fused layers 2+3 + head; GEMMs on fp16 MMA ----------------
__global__ void __launch_bounds__(256) k_layer23(
    const float* __restrict__ b2,
    const float* __restrict__ g2, const float* __restrict__ be2,
    const float* __restrict__ m2, const float* __restrict__ v2,
    const float* __restrict__ b3,
    const float* __restrict__ g3, const float* __restrict__ be3,
    const float* __restrict__ m3, const float* __restrict__ v3,
    const float* __restrict__ fcw, const float* __restrict__ fcb,
    float* __restrict__ out)
{
    extern __shared__ float sm[];
    float* Ag = sm;              // 64 x 65
    float* Zs = sm + 4160;       // 64 x 132 fp32 (later 64 x 68)
    __half* Hh = reinterpret_cast<__half*>(sm + 12608);   // 64 x 136 halves

    const int tid = threadIdx.x;
    const int g   = blockIdx.x;
    const int warp = tid >> 5, lane = tid & 31;
    const int wm = warp >> 2, wn = warp & 3;
    const int gID = lane >> 2, tig = lane & 3;
    const int tx = tid & 15, ty = tid >> 4;

    for (int i = tid; i < 4096; i += 256)
        Ag[(i >> 6)*65 + (i & 63)] = g_A[(size_t)g*4096 + i];
    {
        const uint4* src = reinterpret_cast<const uint4*>(g_h1 + (size_t)g * 64 * HIDc);
        for (int i = tid; i < 1024; i += 256) {
            int row = i >> 4, c8 = i & 15;
            *reinterpret_cast<uint4*>(Hh + row*136 + c8*8) = src[i];
        }
    }
    __syncthreads();

    // ---- phase 1 (MMA): Z2 = H1 @ W2 ----
    float acc[2][4][4];
#pragma unroll
    for (int mi = 0; mi < 2; mi++)
#pragma unroll
        for (int j = 0; j < 4; j++)
#pragma unroll
            for (int c = 0; c < 4; c++) acc[mi][j][c] = 0.f;
#pragma unroll
    for (int k16 = 0; k16 < 8; k16++) {
        const int k0 = k16 * 16;
        uint32_t a[2][4];
#pragma unroll
        for (int mi = 0; mi < 2; mi++) {
            int row = wm*32 + mi*16 + gID;
            a[mi][0] = *reinterpret_cast<const uint32_t*>(Hh + row*136     + k0 + 2*tig);
            a[mi][1] = *reinterpret_cast<const uint32_t*>(Hh + (row+8)*136 + k0 + 2*tig);
            a[mi][2] = *reinterpret_cast<const uint32_t*>(Hh + row*136     + k0 + 8 + 2*tig);
            a[mi][3] = *reinterpret_cast<const uint32_t*>(Hh + (row+8)*136 + k0 + 8 + 2*tig);
        }
#pragma unroll
        for (int j = 0; j < 4; j++) {
            int n = wn*32 + j*8 + gID;
            uint32_t b0 = __ldg(reinterpret_cast<const uint32_t*>(g_W2t + n*HIDc + k0 + 2*tig));
            uint32_t b1 = __ldg(reinterpret_cast<const uint32_t*>(g_W2t + n*HIDc + k0 + 8 + 2*tig));
            mma_f16(acc[0][j], a[0], b0, b1);
            mma_f16(acc[1][j], a[1], b0, b1);
        }
    }
    __syncthreads();
#pragma unroll
    for (int mi = 0; mi < 2; mi++)
#pragma unroll
        for (int j = 0; j < 4; j++) {
            int row = wm*32 + mi*16 + gID;
            int col = wn*32 + j*8 + 2*tig;
            *reinterpret_cast<float2*>(Zs + row*132 + col) =
                make_float2(acc[mi][j][0], acc[mi][j][1]);
            *reinterpret_cast<float2*>(Zs + (row+8)*132 + col) =
                make_float2(acc[mi][j][2], acc[mi][j][3]);
        }
    __syncthreads();

    // ---- phase 2 (fp32): H2 = relu(BN2(A@Z2 + b2)) -> Hh (fp16) ----
    {
        float ac[4][8];
#pragma unroll
        for (int r = 0; r < 4; r++)
#pragma unroll
            for (int j = 0; j < 8; j++) ac[r][j] = 0.f;
#pragma unroll 4
        for (int k = 0; k < 64; k++) {
            float a[4];
#pragma unroll
            for (int r = 0; r < 4; r++) a[r] = Ag[(ty*4 + r)*65 + k];
            float zz[8];
            *reinterpret_cast<float4*>(zz)     = *reinterpret_cast<const float4*>(Zs + k*132 + tx*8);
            *reinterpret_cast<float4*>(zz + 4) = *reinterpret_cast<const float4*>(Zs + k*132 + tx*8 + 4);
#pragma unroll
            for (int r = 0; r < 4; r++)
#pragma unroll
                for (int j = 0; j < 8; j++)
                    ac[r][j] = fmaf(a[r], zz[j], ac[r][j]);
        }
        float sc[8], sh[8];
#pragma unroll
        for (int j = 0; j < 8; j++) {
            int col = tx*8 + j;
            float s = g2[col] * rsqrtf(v2[col] + EPSf);
            sc[j] = s;
            sh[j] = (b2[col] - m2[col]) * s + be2[col];
        }
#pragma unroll
        for (int r = 0; r < 4; r++) {
            float v[8];
#pragma unroll
            for (int j = 0; j < 8; j++)
                v[j] = fmaxf(fmaf(ac[r][j], sc[j], sh[j]), 0.f);
            __half2* d = reinterpret_cast<__half2*>(Hh + (ty*4 + r)*136 + tx*8);
            d[0] = __floats2half2_rn(v[0], v[1]);
            d[1] = __floats2half2_rn(v[2], v[3]);
            d[2] = __floats2half2_rn(v[4], v[5]);
            d[3] = __floats2half2_rn(v[6], v[7]);
        }
    }
    __syncthreads();

    // ---- phase 3 (MMA): Z3 = H2 @ W3 ----
    float ac3[2][2][4];
#pragma unroll
    for (int mi = 0; mi < 2; mi++)
#pragma unroll
        for (int j = 0; j < 2; j++)
#pragma unroll
            for (int c = 0; c < 4; c++) ac3[mi][j][c] = 0.f;
#pragma unroll
    for (int k16 = 0; k16 < 8; k16++) {
        const int k0 = k16 * 16;
        uint32_t a[2][4];
#pragma unroll
        for (int mi = 0; mi < 2; mi++) {
            int row = wm*32 + mi*16 + gID;
            a[mi][0] = *reinterpret_cast<const uint32_t*>(Hh + row*136     + k0 + 2*tig);
            a[mi][1] = *reinterpret_cast<const uint32_t*>(Hh + (row+8)*136 + k0 + 2*tig);
            a[mi][2] = *reinterpret_cast<const uint32_t*>(Hh + row*136     + k0 + 8 + 2*tig);
            a[mi][3] = *reinterpret_cast<const uint32_t*>(Hh + (row+8)*136 + k0 + 8 + 2*tig);
        }
#pragma unroll
        for (int j = 0; j < 2; j++) {
            int n = wn*16 + j*8 + gID;
            uint32_t b0 = __ldg(reinterpret_cast<const uint32_t*>(g_W3t + n*HIDc + k0 + 2*tig));
            uint32_t b1 = __ldg(reinterpret_cast<const uint32_t*>(g_W3t + n*HIDc + k0 + 8 + 2*tig));
            mma_f16(ac3[0][j], a[0], b0, b1);
            mma_f16(ac3[1][j], a[1], b0, b1);
        }
    }
    __syncthreads();
#pragma unroll
    for (int mi = 0; mi < 2; mi++)
#pragma unroll
        for (int j = 0; j < 2; j++) {
            int row = wm*32 + mi*16 + gID;
            int col = wn*16 + j*8 + 2*tig;
            *reinterpret_cast<float2*>(Zs + row*68 + col) =
                make_float2(ac3[mi][j][0], ac3[mi][j][1]);
            *reinterpret_cast<float2*>(Zs + (row+8)*68 + col) =
                make_float2(ac3[mi][j][2], ac3[mi][j][3]);
        }
    __syncthreads();

    // ---- phase 4 (fp32): Y3 = relu(BN3(A@Z3 + b3)) -> Ys ----
    float* Ys = reinterpret_cast<float*>(Hh);
    {
        float ac[4][4];
#pragma unroll
        for (int r = 0; r < 4; r++)
#pragma unroll
            for (int j = 0; j < 4; j++) ac[r][j] = 0.f;
#pragma unroll 4
        for (int k = 0; k < 64; k++) {
            float a[4];
#pragma unroll
            for (int r = 0; r < 4; r++) a[r] = Ag[(ty*4 + r)*65 + k];
            float zz[4];
            *reinterpret_cast<float4*>(zz) = *reinterpret_cast<const float4*>(Zs + k*68 + tx*4);
#pragma unroll
            for (int r = 0; r < 4; r++)
#pragma unroll
                for (int j = 0; j < 4; j++)
                    ac[r][j] = fmaf(a[r], zz[j], ac[r][j]);
        }
        float sc[4], sh[4];
#pragma unroll
        for (int j = 0; j < 4; j++) {
            int col = tx*4 + j;
            float s = g3[col] * rsqrtf(v3[col] + EPSf);
            sc[j] = s;
            sh[j] = (b3[col] - m3[col]) * s + be3[col];
        }
        __syncthreads();
#pragma unroll
        for (int r = 0; r < 4; r++)
#pragma unroll
            for (int j = 0; j < 4; j++)
                Ys[(ty*4 + r)*64 + tx*4 + j] = fmaxf(fmaf(ac[r][j], sc[j], sh[j]), 0.f);
    }
    __syncthreads();

    // ---- pool + FC + log_softmax ----
    float* pooled = Ag;
    if (tid < 64) {
        float s = 0.f;
#pragma unroll 8
        for (int i = 0; i < 64; i++) s += Ys[i*64 + tid];
        pooled[tid] = s * (1.0f / 64.0f);
    }
    __syncthreads();
    if (tid < 2) {
        float l = fcb[tid];
#pragma unroll 8
        for (int j = 0; j < 64; j++) l = fmaf(pooled[j], fcw[j*2 + tid], l);
        pooled[64 + tid] = l;
    }
    __syncthreads();
    if (tid == 0) {
        float l0 = pooled[64], l1 = pooled[65];
        float m  = fmaxf(l0, l1);
        float lse = m + logf(expf(l0 - m) + expf(l1 - m));
        out[g*2 + 0] = l0 - lse;
        out[g*2 + 1] = l1 - lse;
    }
}

// ---------------- host launcher ----------------
extern "C" void kernel_launch(void* const* d_in, const int* in_sizes, int n_in,
                              void* d_out, int out_size) {
    const float* x   = (const float*)d_in[0];
    const int*   ei  = (const int*)  d_in[1];
    const float* ea  = (const float*)d_in[2];
    const float* cw  = (const float*)d_in[4];
    const float* cb  = (const float*)d_in[5];
    const float* W1  = (const float*)d_in[6];
    const float* b1  = (const float*)d_in[7];
    const float* W2  = (const float*)d_in[8];
    const float* b2  = (const float*)d_in[9];
    const float* W3  = (const float*)d_in[10];
    const float* b3  = (const float*)d_in[11];
    const float* g1  = (const float*)d_in[12];
    const float* be1 = (const float*)d_in[13];
    const float* m1  = (const float*)d_in[14];
    const float* v1  = (const float*)d_in[15];
    const float* g2  = (const float*)d_in[16];
    const float* be2 = (const float*)d_in[17];
    const float* m2  = (const float*)d_in[18];
    const float* v2  = (const float*)d_in[19];
    const float* g3  = (const float*)d_in[20];
    const float* be3 = (const float*)d_in[21];
    const float* m3  = (const float*)d_in[22];
    const float* v3  = (const float*)d_in[23];
    const float* fcw = (const float*)d_in[24];
    const float* fcb = (const float*)d_in[25];
    float* out = (float*)d_out;

    const int* srcp = ei;
    const int* dstp = ei + Ec;

    k_buildA<<<NG, 256>>>(srcp, dstp, ea);
    {
        dim3 tb(32, 8);
        dim3 gb(FINc/32, HIDc/32);
        k_wt<<<gb, tb>>>(W1);
    }
    {
        int tot = 32*WCP + HIDc*HIDc + OUT3c*HIDc;
        k_wprep<<<(tot + 255)/256, 256>>>(cw, W2, W3);
    }
    k_conv_tc<<<Nn, 128>>>(x, cb);

    const int smemL1 = (128*130 + 2*64*65) * 4;   // 99840 B
    cudaFuncSetAttribute((const void*)k_layer1_hf,
                         cudaFuncAttributeMaxDynamicSharedMemorySize, smemL1);
    k_layer1_hf<<<NG/2, 256, smemL1>>>(b1, g1, be1, m1, v1);

    const int smemL23 = 16960 * 4;   // 67840 B
    cudaFuncSetAttribute((const void*)k_layer23,
                         cudaFuncAttributeMaxDynamicSharedMemorySize, smemL23);
    k_layer23<<<NG, 256, smemL23>>>(b2, g2, be2, m2, v2,
                                    b3, g3, be3, m3, v3, fcw, fcb, out);
}

// round 14
// speedup vs baseline: 1.1738x; 1.0511x over previous
#include <cuda_runtime.h>
#include <cuda_fp16.h>
#include <math.h>
#include <stdint.h>

// ---------------- problem constants ----------------
#define Nn      32768
#define Ll      3000
#define PERG    64
#define NG      512          // Nn / PERG
#define DEGc    16
#define Ec      (Nn*DEGc)    // 524288
#define HIDc    128
#define OUT3c   64
#define REDc    146
#define FINc    4672         // 32*146
#define EPSf    1e-5f
#define TILES   146          // FINc / 32
#define WCP     120          // conv weight pitch (halves)

// ---------------- device scratch (static, no allocs) ----------------
__device__ float g_A[NG*64*64];                 // 8 MB
__device__ __half g_h0[(size_t)Nn * FINc];      // 306 MB (fp16 conv output)
__device__ __half g_h1[(size_t)Nn * HIDc];      // 8 MB (fp16 layer1 output)
__device__ __half g_Wt[(size_t)HIDc * FINc];    // 1.2 MB: W1^T, fp16
__device__ __half g_Wch[32*WCP];                // conv weights fp16, pitch 120
__device__ __half g_W2t[HIDc*HIDc];             // W2^T [n][k] fp16
__device__ __half g_W3t[OUT3c*HIDc];            // W3^T [n][k] fp16

// ---------------- helpers ----------------
__device__ __forceinline__ uint32_t smem_u32(const void* p) {
    uint32_t a;
    asm("{ .reg .u64 t; cvta.to.shared.u64 t, %1; cvt.u32.u64 %0, t; }" : "=r"(a) : "l"(p));
    return a;
}
__device__ __forceinline__ void mma_f16(float* d, const uint32_t* a, uint32_t b0, uint32_t b1) {
    asm volatile(
        "mma.sync.aligned.m16n8k16.row.col.f32.f16.f16.f32 "
        "{%0,%1,%2,%3}, {%4,%5,%6,%7}, {%8,%9}, {%0,%1,%2,%3};"
        : "+f"(d[0]), "+f"(d[1]), "+f"(d[2]), "+f"(d[3])
        : "r"(a[0]), "r"(a[1]), "r"(a[2]), "r"(a[3]), "r"(b0), "r"(b1));
}
__device__ __forceinline__ void cp16(uint32_t dst, const void* src) {
    asm volatile("cp.async.cg.shared.global [%0], [%1], 16;" :: "r"(dst), "l"(src));
}
#define CP_COMMIT() asm volatile("cp.async.commit_group;" ::: "memory")
#define CP_WAIT1()  asm volatile("cp.async.wait_group 1;" ::: "memory")
__device__ __forceinline__ uint32_t h2u(__half2 h) {
    return *reinterpret_cast<uint32_t*>(&h);
}

// ---------------- per-graph aggregation matrix (deg computed locally) ----------------
__global__ void __launch_bounds__(256) k_buildA(const int* __restrict__ src,
                                                const int* __restrict__ dst,
                                                const float* __restrict__ w) {
    __shared__ float sA[64*64];
    __shared__ float sdeg[64];
    const int g = blockIdx.x, tid = threadIdx.x;
    for (int i = tid; i < 4096; i += 256) sA[i] = 0.f;
    if (tid < 64) sdeg[tid] = 1.0f;
    __syncthreads();
    const int base = g * (PERG * DEGc);
    for (int e = tid; e < PERG*DEGc; e += 256)
        atomicAdd(&sdeg[dst[base + e] - g*64], w[base + e]);
    __syncthreads();
    if (tid < 64) sdeg[tid] = rsqrtf(sdeg[tid]);
    __syncthreads();
    for (int e = tid; e < PERG*DEGc; e += 256) {
        int s = src[base + e] - g*64;
        int d = dst[base + e] - g*64;
        atomicAdd(&sA[d*64 + s], sdeg[s] * w[base + e] * sdeg[d]);
    }
    __syncthreads();
    if (tid < 64) { float di = sdeg[tid]; sA[tid*64 + tid] += di*di; }
    __syncthreads();
    for (int i = tid; i < 4096; i += 256) g_A[g*4096 + i] = sA[i];
}

// ---------------- W1 transpose + fp16 round ----------------
__global__ void k_wt(const float* __restrict__ W) {
    __shared__ float t[32][33];
    int k0 = blockIdx.x * 32, n0 = blockIdx.y * 32;
    int tx = threadIdx.x, ty = threadIdx.y;           // 32 x 8
    for (int r = 0; r < 32; r += 8)
        t[ty + r][tx] = W[(size_t)(k0 + ty + r) * HIDc + n0 + tx];
    __syncthreads();
    for (int r = 0; r < 32; r += 8)
        g_Wt[(size_t)(n0 + ty + r) * FINc + k0 + tx] = __float2half_rn(t[tx][ty + r]);
}

// ---------------- weight prep: conv weights + W2^T + W3^T ----------------
__global__ void k_wprep(const float* __restrict__ cw,
                        const float* __restrict__ W2,
                        const float* __restrict__ W3) {
    int i = blockIdx.x * blockDim.x + threadIdx.x;
    if (i < 32*WCP) {
        int c = i / WCP, t = i % WCP;
        g_Wch[i] = __float2half_rn((t < 100) ? cw[c*100 + t] : 0.f);
    }
    int j = i - 32*WCP;
    if (j >= 0 && j < HIDc*HIDc) {
        int n = j >> 7, k = j & 127;
        g_W2t[j] = __float2half_rn(W2[k*HIDc + n]);
    }
    int l = j - HIDc*HIDc;
    if (l >= 0 && l < OUT3c*HIDc) {
        int n = l >> 7, k = l & 127;
        g_W3t[l] = __float2half_rn(W3[k*OUT3c + n]);
    }
}

// ---------------- Conv1d via mma.sync fp16 (m16n8k16), fp16 output ----------------
// One CTA (128 thr, 4 warps) per node. M=32 filters, N=160 p (warp=40),
// K=112 (7 k16 steps). B fragment = implicit im2col: B[k=t][n=p] = xs[20p + t].
// launch_bounds minBlocks=8 forces regs<=64 -> 8 CTAs/SM (occ 50%).
__global__ void __launch_bounds__(128, 8) k_conv_tc(const float* __restrict__ x,
                                                    const float* __restrict__ cb) {
    __shared__ __half sbuf[3304 + 32*WCP];   // xs [0,3304) ; ws [3304,+3840)
    __half* xs = sbuf;
    __half* ws = sbuf + 3304;
    const int n    = blockIdx.x;
    const int tid  = threadIdx.x;
    const int warp = tid >> 5, lane = tid & 31;
    const int gID  = lane >> 2, tig = lane & 3;

    {
        const float4* x4 = reinterpret_cast<const float4*>(x + (size_t)n * Ll);
        for (int i = tid; i < 750; i += 128) {
            float4 v = x4[i];
            __half2* d = reinterpret_cast<__half2*>(xs + i*4);
            d[0] = __floats2half2_rn(v.x, v.y);
            d[1] = __floats2half2_rn(v.z, v.w);
        }
        __half2 z2 = __floats2half2_rn(0.f, 0.f);
        for (int i = 1500 + tid; i < 1652; i += 128)
            reinterpret_cast<__half2*>(xs)[i] = z2;
        const uint4* w4 = reinterpret_cast<const uint4*>(g_Wch);
        uint4* ws4 = reinterpret_cast<uint4*>(ws);
        for (int i = tid; i < 480; i += 128) ws4[i] = w4[i];
    }
    __syncthreads();

    float acc[2][5][4];
#pragma unroll
    for (int mi = 0; mi < 2; mi++)
#pragma unroll
        for (int nt = 0; nt < 5; nt++)
#pragma unroll
            for (int c = 0; c < 4; c++) acc[mi][nt][c] = 0.f;

    const int pbase = warp * 40;
#pragma unroll
    for (int k16 = 0; k16 < 7; k16++) {
        const int k0 = k16 * 16;
        uint32_t a[2][4];
#pragma unroll
        for (int mi = 0; mi < 2; mi++) {
            const int c = mi*16 + gID;
            a[mi][0] = *reinterpret_cast<const uint32_t*>(ws + c*WCP     + k0 + 2*tig);
            a[mi][1] = *reinterpret_cast<const uint32_t*>(ws + (c+8)*WCP + k0 + 2*tig);
            a[mi][2] = *reinterpret_cast<const uint32_t*>(ws + c*WCP     + k0 + 8 + 2*tig);
            a[mi][3] = *reinterpret_cast<const uint32_t*>(ws + (c+8)*WCP + k0 + 8 + 2*tig);
        }
#pragma unroll
        for (int nt = 0; nt < 5; nt++) {
            const int p = pbase + nt*8 + gID;
            uint32_t b0 = *reinterpret_cast<const uint32_t*>(xs + 20*p + k0 + 2*tig);
            uint32_t b1 = *reinterpret_cast<const uint32_t*>(xs + 20*p + k0 + 8 + 2*tig);
            mma_f16(acc[0][nt], a[0], b0, b1);
            mma_f16(acc[1][nt], a[1], b0, b1);
        }
    }

    float bc[2][2];
#pragma unroll
    for (int mi = 0; mi < 2; mi++) {
        bc[mi][0] = cb[mi*16 + gID];
        bc[mi][1] = cb[mi*16 + gID + 8];
    }
    __syncthreads();
    __half* sout = sbuf;                   // 4672 fp16 [c][p]
#pragma unroll
    for (int mi = 0; mi < 2; mi++)
#pragma unroll
        for (int nt = 0; nt < 5; nt++) {
            const int c0 = mi*16 + gID, c1 = c0 + 8;
            const int p0 = pbase + nt*8 + 2*tig;
            if (p0 < REDc) {
                bool two = (p0 + 1 < REDc);
                float v00 = fmaxf(acc[mi][nt][0] + bc[mi][0], 0.f);
                float v01 = two ? fmaxf(acc[mi][nt][1] + bc[mi][0], 0.f) : 0.f;
                float v10 = fmaxf(acc[mi][nt][2] + bc[mi][1], 0.f);
                float v11 = two ? fmaxf(acc[mi][nt][3] + bc[mi][1], 0.f) : 0.f;
                if (two) {
                    *reinterpret_cast<__half2*>(sout + c0*REDc + p0) = __floats2half2_rn(v00, v01);
                    *reinterpret_cast<__half2*>(sout + c1*REDc + p0) = __floats2half2_rn(v10, v11);
                } else {
                    sout[c0*REDc + p0] = __float2half_rn(v00);
                    sout[c1*REDc + p0] = __float2half_rn(v10);
                }
            }
        }
    __syncthreads();
    uint4* o4 = reinterpret_cast<uint4*>(g_h0 + (size_t)n * FINc);
    const uint4* so4 = reinterpret_cast<const uint4*>(sout);
    for (int i = tid; i < 584; i += 128) o4[i] = so4[i];
}

// ---------------- layer1 via mma.sync fp16 (m16n8k16), fp16 output ----------------
__global__ void __launch_bounds__(256, 2) k_layer1_hf(
    const float* __restrict__ bias,
    const float* __restrict__ gam, const float* __restrict__ bet,
    const float* __restrict__ mean, const float* __restrict__ var)
{
    extern __shared__ float smf[];
    const uint32_t sb = smem_u32(smf);
    const int tid  = threadIdx.x;
    const int b    = blockIdx.x;
    const int warp = tid >> 5, lane = tid & 31;
    const int wm   = warp >> 1, wn = warp & 1;
    const int gID  = lane >> 2, tig = lane & 3;

    const __half* Ap = g_h0 + (size_t)b * 128 * FINc;
    const int lr = tid >> 1;
    const int lc = (tid & 1) * 16;

    auto issue = [&](int i) {
        const int s = i & 1;
        const int k0 = i * 32;
        const uint32_t stb = sb + (uint32_t)s * 20480u;
#pragma unroll
        for (int q = 0; q < 2; q++) {
            int c = lc + q * 8;
            uint32_t o = (uint32_t)(lr * 80 + c * 2);
            cp16(stb + o,          Ap   + (size_t)lr * FINc + k0 + c);
            cp16(stb + 10240u + o, g_Wt + (size_t)lr * FINc + k0 + c);
        }
    };

    float acc[2][8][4];
#pragma unroll
    for (int mi = 0; mi < 2; mi++)
#pragma unroll
        for (int j = 0; j < 8; j++)
#pragma unroll
            for (int c = 0; c < 4; c++) acc[mi][j][c] = 0.f;

    issue(0); CP_COMMIT();
    issue(1); CP_COMMIT();

    for (int i = 0; i < TILES; i++) {
        CP_WAIT1();
        __syncthreads();
        const __half* As = reinterpret_cast<const __half*>(
            reinterpret_cast<const char*>(smf) + (i & 1) * 20480);
        const __half* Bs = As + 5120;
#pragma unroll
        for (int kk = 0; kk < 2; kk++) {
            const int k0 = kk * 16;
            uint32_t a[2][4];
#pragma unroll
            for (int mi = 0; mi < 2; mi++) {
                int row = wm*32 + mi*16 + gID;
                a[mi][0] = *reinterpret_cast<const uint32_t*>(As + row*40     + k0 + 2*tig);
                a[mi][1] = *reinterpret_cast<const uint32_t*>(As + (row+8)*40 + k0 + 2*tig);
                a[mi][2] = *reinterpret_cast<const uint32_t*>(As + row*40     + k0 + 8 + 2*tig);
                a[mi][3] = *reinterpret_cast<const uint32_t*>(As + (row+8)*40 + k0 + 8 + 2*tig);
            }
#pragma unroll
            for (int j = 0; j < 8; j++) {
                int n = wn*64 + j*8 + gID;
                uint32_t b0 = *reinterpret_cast<const uint32_t*>(Bs + n*40 + k0 + 2*tig);
                uint32_t b1 = *reinterpret_cast<const uint32_t*>(Bs + n*40 + k0 + 8 + 2*tig);
                mma_f16(acc[0][j], a[0], b0, b1);
                mma_f16(acc[1][j], a[1], b0, b1);
            }
        }
        __syncthreads();
        if (i + 2 < TILES) issue(i + 2);
        CP_COMMIT();
    }

    __syncthreads();
    float* Zs = smf;                               // 128 x 130
    float* Ag = smf + 16640;                       // 2 x (64 x 65)
#pragma unroll
    for (int mi = 0; mi < 2; mi++)
#pragma unroll
        for (int j = 0; j < 8; j++) {
            int row = wm*32 + mi*16 + gID;
            int col = wn*64 + j*8 + 2*tig;
            *reinterpret_cast<float2*>(Zs + row*130 + col) =
                make_float2(acc[mi][j][0], acc[mi][j][1]);
            *reinterpret_cast<float2*>(Zs + (row+8)*130 + col) =
                make_float2(acc[mi][j][2], acc[mi][j][3]);
        }
    {
        const float* gA = g_A + (size_t)(2*b) * 4096;
        for (int i2 = tid; i2 < 8192; i2 += 256) {
            int gg = i2 >> 12, rr = (i2 >> 6) & 63, cc = i2 & 63;
            Ag[gg*4160 + rr*65 + cc] = gA[(size_t)gg*4096 + rr*64 + cc];
        }
    }
    __syncthreads();

    {
        const int gg = tid >> 7;
        const int t  = tid & 127;
        const int tx = t & 15;
        const int ty = t >> 4;
        float ac[8][8];
#pragma unroll
        for (int r = 0; r < 8; r++)
#pragma unroll
            for (int j = 0; j < 8; j++) ac[r][j] = 0.f;

        const float* Agg = Ag + gg * 4160;
        const float* Zg  = Zs + gg * 64 * 130;
#pragma unroll 4
        for (int k = 0; k < 64; k++) {
            float a[8], z[8];
#pragma unroll
            for (int r = 0; r < 8; r++) a[r] = Agg[(ty*8 + r)*65 + k];
#pragma unroll
            for (int j = 0; j < 8; j++) z[j] = Zg[k*130 + tx*8 + j];
#pragma unroll
            for (int r = 0; r < 8; r++)
#pragma unroll
                for (int j = 0; j < 8; j++)
                    ac[r][j] = fmaf(a[r], z[j], ac[r][j]);
        }
        float sc[8], sh[8];
#pragma unroll
        for (int j = 0; j < 8; j++) {
            int col = tx*8 + j;
            float s = gam[col] * rsqrtf(var[col] + EPSf);
            sc[j] = s;
            sh[j] = (bias[col] - mean[col]) * s + bet[col];
        }
#pragma unroll
        for (int r = 0; r < 8; r++) {
            float v[8];
#pragma unroll
            for (int j = 0; j < 8; j++)
                v[j] = fmaxf(fmaf(ac[r][j], sc[j], sh[j]), 0.f);
            uint4 pk;
            pk.x = h2u(__floats2half2_rn(v[0], v[1]));
            pk.y = h2u(__floats2half2_rn(v[2], v[3]));
            pk.z = h2u(__floats2half2_rn(v[4], v[5]));
            pk.w = h2u(__floats2half2_rn(v[6], v[7]));
            *reinterpret_cast<uint4*>(g_h1 + (size_t)(b*128 + gg*64 + ty*8 + r)*HIDc + tx*8) = pk;
        }
    }
}

// ---------------- fused layers 2+3 + head; GEMMs on fp16 MMA ----------------
__global__ void __launch_bounds__(256) k_layer23(
    const float* __restrict__ b2,
    const float* __restrict__ g2, const float* __restrict__ be2,
    const float* __restrict__ m2, const float* __restrict__ v2,
    const float* __restrict__ b3,
    const float* __restrict__ g3, const float* __restrict__ be3,
    const float* __restrict__ m3, const float* __restrict__ v3,
    const float* __restrict__ fcw, const float* __restrict__ fcb,
    float* __restrict__ out)
{
    extern __shared__ float sm[];
    float* Ag = sm;              // 64 x 65
    float* Zs = sm + 4160;       // 64 x 132 fp32 (later 64 x 68)
    __half* Hh = reinterpret_cast<__half*>(sm + 12608);   // 64 x 136 halves

    const int tid = threadIdx.x;
    const int g   = blockIdx.x;
    const int warp = tid >> 5, lane = tid & 31;
    const int wm = warp >> 2, wn = warp & 3;
    const int gID = lane >> 2, tig = lane & 3;
    const int tx = tid & 15, ty = tid >> 4;

    for (int i = tid; i < 4096; i += 256)
        Ag[(i >> 6)*65 + (i & 63)] = g_A[(size_t)g*4096 + i];
    {
        const uint4* src = reinterpret_cast<const uint4*>(g_h1 + (size_t)g * 64 * HIDc);
        for (int i = tid; i < 1024; i += 256) {
            int row = i >> 4, c8 = i & 15;
            *reinterpret_cast<uint4*>(Hh + row*136 + c8*8) = src[i];
        }
    }
    __syncthreads();

    // ---- phase 1 (MMA): Z2 = H1 @ W2 ----
    float acc[2][4][4];
#pragma unroll
    for (int mi = 0; mi < 2; mi++)
#pragma unroll
        for (int j = 0; j < 4; j++)
#pragma unroll
            for (int c = 0; c < 4; c++) acc[mi][j][c] = 0.f;
#pragma unroll
    for (int k16 = 0; k16 < 8; k16++) {
        const int k0 = k16 * 16;
        uint32_t a[2][4];
#pragma unroll
        for (int mi = 0; mi < 2; mi++) {
            int row = wm*32 + mi*16 + gID;
            a[mi][0] = *reinterpret_cast<const uint32_t*>(Hh + row*136     + k0 + 2*tig);
            a[mi][1] = *reinterpret_cast<const uint32_t*>(Hh + (row+8)*136 + k0 + 2*tig);
            a[mi][2] = *reinterpret_cast<const uint32_t*>(Hh + row*136     + k0 + 8 + 2*tig);
            a[mi][3] = *reinterpret_cast<const uint32_t*>(Hh + (row+8)*136 + k0 + 8 + 2*tig);
        }
#pragma unroll
        for (int j = 0; j < 4; j++) {
            int n = wn*32 + j*8 + gID;
            uint32_t b0 = __ldg(reinterpret_cast<const uint32_t*>(g_W2t + n*HIDc + k0 + 2*tig));
            uint32_t b1 = __ldg(reinterpret_cast<const uint32_t*>(g_W2t + n*HIDc + k0 + 8 + 2*tig));
            mma_f16(acc[0][j], a[0], b0, b1);
            mma_f16(acc[1][j], a[1], b0, b1);
        }
    }
    __syncthreads();
#pragma unroll
    for (int mi = 0; mi < 2; mi++)
#pragma unroll
        for (int j = 0; j < 4; j++) {
            int row = wm*32 + mi*16 + gID;
            int col = wn*32 + j*8 + 2*tig;
            *reinterpret_cast<float2*>(Zs + row*132 + col) =
                make_float2(acc[mi][j][0], acc[mi][j][1]);
            *reinterpret_cast<float2*>(Zs + (row+8)*132 + col) =
                make_float2(acc[mi][j][2], acc[mi][j][3]);
        }
    __syncthreads();

    // ---- phase 2 (fp32): H2 = relu(BN2(A@Z2 + b2)) -> Hh (fp16) ----
    {
        float ac[4][8];
#pragma unroll
        for (int r = 0; r < 4; r++)
#pragma unroll
            for (int j = 0; j < 8; j++) ac[r][j] = 0.f;
#pragma unroll 4
        for (int k = 0; k < 64; k++) {
            float a[4];
#pragma unroll
            for (int r = 0; r < 4; r++) a[r] = Ag[(ty*4 + r)*65 + k];
            float zz[8];
            *reinterpret_cast<float4*>(zz)     = *reinterpret_cast<const float4*>(Zs + k*132 + tx*8);
            *reinterpret_cast<float4*>(zz + 4) = *reinterpret_cast<const float4*>(Zs + k*132 + tx*8 + 4);
#pragma unroll
            for (int r = 0; r < 4; r++)
#pragma unroll
                for (int j = 0; j < 8; j++)
                    ac[r][j] = fmaf(a[r], zz[j], ac[r][j]);
        }
        float sc[8], sh[8];
#pragma unroll
        for (int j = 0; j < 8; j++) {
            int col = tx*8 + j;
            float s = g2[col] * rsqrtf(v2[col] + EPSf);
            sc[j] = s;
            sh[j] = (b2[col] - m2[col]) * s + be2[col];
        }
#pragma unroll
        for (int r = 0; r < 4; r++) {
            float v[8];
#pragma unroll
            for (int j = 0; j < 8; j++)
                v[j] = fmaxf(fmaf(ac[r][j], sc[j], sh[j]), 0.f);
            __half2* d = reinterpret_cast<__half2*>(Hh + (ty*4 + r)*136 + tx*8);
            d[0] = __floats2half2_rn(v[0], v[1]);
            d[1] = __floats2half2_rn(v[2], v[3]);
            d[2] = __floats2half2_rn(v[4], v[5]);
            d[3] = __floats2half2_rn(v[6], v[7]);
        }
    }
    __syncthreads();

    // ---- phase 3 (MMA): Z3 = H2 @ W3 ----
    float ac3[2][2][4];
#pragma unroll
    for (int mi = 0; mi < 2; mi++)
#pragma unroll
        for (int j = 0; j < 2; j++)
#pragma unroll
            for (int c = 0; c < 4; c++) ac3[mi][j][c] = 0.f;
#pragma unroll
    for (int k16 = 0; k16 < 8; k16++) {
        const int k0 = k16 * 16;
        uint32_t a[2][4];
#pragma unroll
        for (int mi = 0; mi < 2; mi++) {
            int row = wm*32 + mi*16 + gID;
            a[mi][0] = *reinterpret_cast<const uint32_t*>(Hh + row*136     + k0 + 2*tig);
            a[mi][1] = *reinterpret_cast<const uint32_t*>(Hh + (row+8)*136 + k0 + 2*tig);
            a[mi][2] = *reinterpret_cast<const uint32_t*>(Hh + row*136     + k0 + 8 + 2*tig);
            a[mi][3] = *reinterpret_cast<const uint32_t*>(Hh + (row+8)*136 + k0 + 8 + 2*tig);
        }
#pragma unroll
        for (int j = 0; j < 2; j++) {
            int n = wn*16 + j*8 + gID;
            uint32_t b0 = __ldg(reinterpret_cast<const uint32_t*>(g_W3t + n*HIDc + k0 + 2*tig));
            uint32_t b1 = __ldg(reinterpret_cast<const uint32_t*>(g_W3t + n*HIDc + k0 + 8 + 2*tig));
            mma_f16(ac3[0][j], a[0], b0, b1);
            mma_f16(ac3[1][j], a[1], b0, b1);
        }
    }
    __syncthreads();
#pragma unroll
    for (int mi = 0; mi < 2; mi++)
#pragma unroll
        for (int j = 0; j < 2; j++) {
            int row = wm*32 + mi*16 + gID;
            int col = wn*16 + j*8 + 2*tig;
            *reinterpret_cast<float2*>(Zs + row*68 + col) =
                make_float2(ac3[mi][j][0], ac3[mi][j][1]);
            *reinterpret_cast<float2*>(Zs + (row+8)*68 + col) =
                make_float2(ac3[mi][j][2], ac3[mi][j][3]);
        }
    __syncthreads();

    // ---- phase 4 (fp32): Y3 = relu(BN3(A@Z3 + b3)) -> Ys ----
    float* Ys = reinterpret_cast<float*>(Hh);
    {
        float ac[4][4];
#pragma unroll
        for (int r = 0; r < 4; r++)
#pragma unroll
            for (int j = 0; j < 4; j++) ac[r][j] = 0.f;
#pragma unroll 4
        for (int k = 0; k < 64; k++) {
            float a[4];
#pragma unroll
            for (int r = 0; r < 4; r++) a[r] = Ag[(ty*4 + r)*65 + k];
            float zz[4];
            *reinterpret_cast<float4*>(zz) = *reinterpret_cast<const float4*>(Zs + k*68 + tx*4);
#pragma unroll
            for (int r = 0; r < 4; r++)
#pragma unroll
                for (int j = 0; j < 4; j++)
                    ac[r][j] = fmaf(a[r], zz[j], ac[r][j]);
        }
        float sc[4], sh[4];
#pragma unroll
        for (int j = 0; j < 4; j++) {
            int col = tx*4 + j;
            float s = g3[col] * rsqrtf(v3[col] + EPSf);
            sc[j] = s;
            sh[j] = (b3[col] - m3[col]) * s + be3[col];
        }
        __syncthreads();
#pragma unroll
        for (int r = 0; r < 4; r++)
#pragma unroll
            for (int j = 0; j < 4; j++)
                Ys[(ty*4 + r)*64 + tx*4 + j] = fmaxf(fmaf(ac[r][j], sc[j], sh[j]), 0.f);
    }
    __syncthreads();

    // ---- pool + FC + log_softmax ----
    float* pooled = Ag;
    if (tid < 64) {
        float s = 0.f;
#pragma unroll 8
        for (int i = 0; i < 64; i++) s += Ys[i*64 + tid];
        pooled[tid] = s * (1.0f / 64.0f);
    }
    __syncthreads();
    if (tid < 2) {
        float l = fcb[tid];
#pragma unroll 8
        for (int j = 0; j < 64; j++) l = fmaf(pooled[j], fcw[j*2 + tid], l);
        pooled[64 + tid] = l;
    }
    __syncthreads();
    if (tid == 0) {
        float l0 = pooled[64], l1 = pooled[65];
        float m  = fmaxf(l0, l1);
        float lse = m + logf(expf(l0 - m) + expf(l1 - m));
        out[g*2 + 0] = l0 - lse;
        out[g*2 + 1] = l1 - lse;
    }
}

// ---------------- host launcher ----------------
extern "C" void kernel_launch(void* const* d_in, const int* in_sizes, int n_in,
                              void* d_out, int out_size) {
    const float* x   = (const float*)d_in[0];
    const int*   ei  = (const int*)  d_in[1];
    const float* ea  = (const float*)d_in[2];
    const float* cw  = (const float*)d_in[4];
    const float* cb  = (const float*)d_in[5];
    const float* W1  = (const float*)d_in[6];
    const float* b1  = (const float*)d_in[7];
    const float* W2  = (const float*)d_in[8];
    const float* b2  = (const float*)d_in[9];
    const float* W3  = (const float*)d_in[10];
    const float* b3  = (const float*)d_in[11];
    const float* g1  = (const float*)d_in[12];
    const float* be1 = (const float*)d_in[13];
    const float* m1  = (const float*)d_in[14];
    const float* v1  = (const float*)d_in[15];
    const float* g2  = (const float*)d_in[16];
    const float* be2 = (const float*)d_in[17];
    const float* m2  = (const float*)d_in[18];
    const float* v2  = (const float*)d_in[19];
    const float* g3  = (const float*)d_in[20];
    const float* be3 = (const float*)d_in[21];
    const float* m3  = (const float*)d_in[22];
    const float* v3  = (const float*)d_in[23];
    const float* fcw = (const float*)d_in[24];
    const float* fcb = (const float*)d_in[25];
    float* out = (float*)d_out;

    const int* srcp = ei;
    const int* dstp = ei + Ec;

    k_buildA<<<NG, 256>>>(srcp, dstp, ea);
    {
        dim3 tb(32, 8);
        dim3 gb(FINc/32, HIDc/32);
        k_wt<<<gb, tb>>>(W1);
    }
    {
        int tot = 32*WCP + HIDc*HIDc + OUT3c*HIDc;
        k_wprep<<<(tot + 255)/256, 256>>>(cw, W2, W3);
    }
    k_conv_tc<<<Nn, 128>>>(x, cb);

    const int smemL1 = (128*130 + 2*64*65) * 4;   // 99840 B
    cudaFuncSetAttribute((const void*)k_layer1_hf,
                         cudaFuncAttributeMaxDynamicSharedMemorySize, smemL1);
    k_layer1_hf<<<NG/2, 256, smemL1>>>(b1, g1, be1, m1, v1);

    const int smemL23 = 16960 * 4;   // 67840 B
    cudaFuncSetAttribute((const void*)k_layer23,
                         cudaFuncAttributeMaxDynamicSharedMemorySize, smemL23);
    k_layer23<<<NG, 256, smemL23>>>(b2, g2, be2, m2, v2,
                                    b3, g3, be3, m3, v3, fcw, fcb, out);
}